// round 2
// baseline (speedup 1.0000x reference)
#include <cuda_runtime.h>
#include <cuda_fp16.h>
#include <cstdint>

// Problem constants
#define BB   16
#define HH   112
#define WW   112
#define CIN  128
#define FF   256
#define EE   3
#define HO   110
#define WO   110
#define NPIX (BB*HO*WO)          // 193600 output pixels
#define NPIX_IN (BB*HH*WW)       // 200704 input pixels
#define KD   1152                // 9*128 reduction dim

// GEMM tiling
#define BM 128
#define BN 128
#define BK 32
#define ASTR 40     // padded halves per A-row (80B)
#define BSTR 136    // padded halves per B-row (272B)
#define NKCH (KD/BK)   // 36 K-chunks

// Scratch (device globals: allocation-free rule)
__device__ __half g_xq[(size_t)NPIX_IN * CIN];   // sign(x) as fp16 (+-1), 51.4MB
__device__ float  g_absum[NPIX_IN];              // per-pixel channel |x| sum
__device__ __half g_W[KD * FF];                  // fused weights, K-major [k][f]
__device__ float  g_beta[NPIX];                  // box(|x|)/1152

// ---------------------------------------------------------------------------
// Prep 1: binarize x to fp16 and compute per-pixel channel abs-sum.
// One warp per input pixel; lane handles 4 channels (float4).
// ---------------------------------------------------------------------------
__global__ void prep_x_kernel(const float* __restrict__ x) {
    int warp = (blockIdx.x * blockDim.x + threadIdx.x) >> 5;
    int lane = threadIdx.x & 31;
    if (warp >= NPIX_IN) return;
    const float4 v = *reinterpret_cast<const float4*>(x + (size_t)warp * CIN + lane * 4);
    unsigned s01 = (v.x >= 0.f ? 0x3C00u : 0xBC00u) | ((v.y >= 0.f ? 0x3C00u : 0xBC00u) << 16);
    unsigned s23 = (v.z >= 0.f ? 0x3C00u : 0xBC00u) | ((v.w >= 0.f ? 0x3C00u : 0xBC00u) << 16);
    *reinterpret_cast<uint2*>(g_xq + (size_t)warp * CIN + lane * 4) = make_uint2(s01, s23);
    float a = fabsf(v.x) + fabsf(v.y) + fabsf(v.z) + fabsf(v.w);
    #pragma unroll
    for (int off = 16; off; off >>= 1) a += __shfl_xor_sync(0xffffffffu, a, off);
    if (lane == 0) g_absum[warp] = a;
}

// ---------------------------------------------------------------------------
// Prep 2: fused weight W[k,f] = sum_e alpha[e,f] * sign(K_e[k,f]) in fp16.
// kernels layout [E,3,3,128,256] -> e*KD*FF + k*FF + f
// ---------------------------------------------------------------------------
__global__ void prep_w_kernel(const float* __restrict__ kern,
                              const float* __restrict__ alphas) {
    int idx = blockIdx.x * blockDim.x + threadIdx.x;   // = k*FF + f
    if (idx >= KD * FF) return;
    int f = idx & (FF - 1);
    float acc = 0.f;
    #pragma unroll
    for (int e = 0; e < EE; ++e) {
        float kv = kern[e * (KD * FF) + idx];
        float a  = alphas[e * FF + f];
        acc += (kv >= 0.f) ? a : -a;
    }
    g_W[idx] = __float2half_rn(acc);
}

// ---------------------------------------------------------------------------
// Prep 3: beta = 3x3 box filter of absum / 1152
// ---------------------------------------------------------------------------
__global__ void prep_beta_kernel() {
    int idx = blockIdx.x * blockDim.x + threadIdx.x;
    if (idx >= NPIX) return;
    int b = idx / (HO * WO);
    int r = idx % (HO * WO);
    int h = r / WO, w = r % WO;
    float s = 0.f;
    #pragma unroll
    for (int dh = 0; dh < 3; ++dh)
        #pragma unroll
        for (int dw = 0; dw < 3; ++dw)
            s += g_absum[(b * HH + h + dh) * WW + (w + dw)];
    g_beta[idx] = s * (1.0f / 1152.0f);
}

// ---------------------------------------------------------------------------
// GEMM: out[p,f] = beta[p] * sum_k xq_patch[p,k] * W[k,f]
// Implicit im2col: k = (kh*3+kw)*128 + c ; each BK=32 chunk sits in one tap.
// CTA 128x128, 8 warps (2x4), warp tile 64x32, mma.sync m16n8k16 f32 accum.
// cp.async double-buffered smem.
// ---------------------------------------------------------------------------
__global__ void __launch_bounds__(256) gemm_kernel(float* __restrict__ out) {
    __shared__ __half sA[2][BM * ASTR];
    __shared__ __half sB[2][BK * BSTR];
    __shared__ int    s_pixbase[BM];
    __shared__ float  s_beta[BM];

    const int tid   = threadIdx.x;
    const int mtile = blockIdx.x;
    const int ntile = blockIdx.y;

    if (tid < BM) {
        int p  = mtile * BM + tid;
        int pc = min(p, NPIX - 1);
        int b = pc / (HO * WO);
        int r = pc % (HO * WO);
        int h = r / WO, w = r % WO;
        s_pixbase[tid] = ((b * HH + h) * WW + w) * CIN;
        s_beta[tid]    = g_beta[pc];
    }
    __syncthreads();

    auto load_tiles = [&](int kk, int buf) {
        int tap = kk >> 2;                 // 4 chunks of 32ch per tap
        int c0  = (kk & 3) * 32;
        int dh = tap / 3, dw = tap % 3;
        int xoff = (dh * WW + dw) * CIN + c0;
        // A tile: 128 rows x 64B = 512 x 16B segments
        #pragma unroll
        for (int it = 0; it < 2; ++it) {
            int idx = tid + it * 256;
            int row = idx >> 2, seg = idx & 3;
            const __half* src = g_xq + s_pixbase[row] + xoff + seg * 8;
            unsigned dst = (unsigned)__cvta_generic_to_shared(&sA[buf][row * ASTR + seg * 8]);
            asm volatile("cp.async.ca.shared.global [%0], [%1], 16;\n" :: "r"(dst), "l"(src));
        }
        // B tile: 32 rows x 256B = 512 x 16B segments
        #pragma unroll
        for (int it = 0; it < 2; ++it) {
            int idx = tid + it * 256;
            int row = idx >> 4, seg = idx & 15;
            const __half* src = g_W + (kk * BK + row) * FF + ntile * BN + seg * 8;
            unsigned dst = (unsigned)__cvta_generic_to_shared(&sB[buf][row * BSTR + seg * 8]);
            asm volatile("cp.async.ca.shared.global [%0], [%1], 16;\n" :: "r"(dst), "l"(src));
        }
        asm volatile("cp.async.commit_group;\n");
    };

    float acc[4][4][4];
    #pragma unroll
    for (int i = 0; i < 4; ++i)
        #pragma unroll
        for (int j = 0; j < 4; ++j)
            #pragma unroll
            for (int q = 0; q < 4; ++q) acc[i][j][q] = 0.f;

    const int warp = tid >> 5, lane = tid & 31;
    const int wm = (warp & 1) * 64;   // warp M offset
    const int wn = (warp >> 1) * 32;  // warp N offset
    const int lr = lane & 15;         // ldmatrix row in 16
    const int lc = lane >> 4;         // ldmatrix col-8 selector

    auto compute_tile = [&](int buf) {
        #pragma unroll
        for (int k16 = 0; k16 < 2; ++k16) {
            unsigned a[4][4], bfr[2][4];
            #pragma unroll
            for (int mb = 0; mb < 4; ++mb) {
                unsigned addr = (unsigned)__cvta_generic_to_shared(
                    &sA[buf][(wm + mb * 16 + lr) * ASTR + k16 * 16 + lc * 8]);
                asm volatile("ldmatrix.sync.aligned.m8n8.x4.shared.b16 {%0,%1,%2,%3}, [%4];"
                    : "=r"(a[mb][0]), "=r"(a[mb][1]), "=r"(a[mb][2]), "=r"(a[mb][3]) : "r"(addr));
            }
            #pragma unroll
            for (int nb = 0; nb < 2; ++nb) {
                unsigned addr = (unsigned)__cvta_generic_to_shared(
                    &sB[buf][(k16 * 16 + lr) * BSTR + wn + nb * 16 + lc * 8]);
                asm volatile("ldmatrix.sync.aligned.m8n8.x4.trans.shared.b16 {%0,%1,%2,%3}, [%4];"
                    : "=r"(bfr[nb][0]), "=r"(bfr[nb][1]), "=r"(bfr[nb][2]), "=r"(bfr[nb][3]) : "r"(addr));
            }
            #pragma unroll
            for (int mb = 0; mb < 4; ++mb)
                #pragma unroll
                for (int nb = 0; nb < 4; ++nb) {
                    unsigned b0 = bfr[nb >> 1][(nb & 1) * 2];
                    unsigned b1 = bfr[nb >> 1][(nb & 1) * 2 + 1];
                    asm volatile("mma.sync.aligned.m16n8k16.row.col.f32.f16.f16.f32 "
                        "{%0,%1,%2,%3}, {%4,%5,%6,%7}, {%8,%9}, {%0,%1,%2,%3};"
                        : "+f"(acc[mb][nb][0]), "+f"(acc[mb][nb][1]),
                          "+f"(acc[mb][nb][2]), "+f"(acc[mb][nb][3])
                        : "r"(a[mb][0]), "r"(a[mb][1]), "r"(a[mb][2]), "r"(a[mb][3]),
                          "r"(b0), "r"(b1));
                }
        }
    };

    load_tiles(0, 0);
    int cur = 0;
    for (int kk = 0; kk < NKCH; ++kk) {
        if (kk + 1 < NKCH) {
            load_tiles(kk + 1, cur ^ 1);
            asm volatile("cp.async.wait_group 1;\n");
        } else {
            asm volatile("cp.async.wait_group 0;\n");
        }
        __syncthreads();
        compute_tile(cur);
        __syncthreads();
        cur ^= 1;
    }

    // Epilogue: scale by beta, write f32
    const int g  = lane >> 2;
    const int l2 = (lane & 3) * 2;
    #pragma unroll
    for (int mb = 0; mb < 4; ++mb) {
        int row0l = wm + mb * 16 + g;
        int p0 = mtile * BM + row0l;
        int p1 = p0 + 8;
        float be0 = s_beta[row0l];
        float be1 = s_beta[row0l + 8];
        #pragma unroll
        for (int nb = 0; nb < 4; ++nb) {
            int col = ntile * BN + wn + nb * 8 + l2;
            if (p0 < NPIX) {
                float2 v = make_float2(acc[mb][nb][0] * be0, acc[mb][nb][1] * be0);
                *reinterpret_cast<float2*>(out + (size_t)p0 * FF + col) = v;
            }
            if (p1 < NPIX) {
                float2 v = make_float2(acc[mb][nb][2] * be1, acc[mb][nb][3] * be1);
                *reinterpret_cast<float2*>(out + (size_t)p1 * FF + col) = v;
            }
        }
    }
}

// ---------------------------------------------------------------------------
extern "C" void kernel_launch(void* const* d_in, const int* in_sizes, int n_in,
                              void* d_out, int out_size) {
    const float* x      = (const float*)d_in[0];
    const float* kern   = (const float*)d_in[1];
    const float* alphas = (const float*)d_in[2];
    float* out = (float*)d_out;

    prep_x_kernel<<<NPIX_IN / 8, 256>>>(x);                        // 8 warps/block
    prep_w_kernel<<<(KD * FF + 255) / 256, 256>>>(kern, alphas);
    prep_beta_kernel<<<(NPIX + 255) / 256, 256>>>();

    dim3 grid((NPIX + BM - 1) / BM, FF / BN);                      // (1513, 2)
    gemm_kernel<<<grid, 256>>>(out);
}